// round 1
// baseline (speedup 1.0000x reference)
#include <cuda_runtime.h>
#include <math.h>

// Problem constants (fixed shapes)
#define NS   4000   // sentences
#define SL   128    // sentence length
#define VEC  50     // word vec dim
#define PDIM 5      // pos emb dim
#define EMB  60     // VEC + 2*PDIM
#define HID  230
#define NBAG 500
#define NREL 25
#define LP   132    // padded smem row stride (floats); rows 0..129 used, 130/131 pad

// Intermediate sentence representations h = relu(max_l conv(emb) + b)  [NS, HID]
__device__ float g_h[NS * HID];

// ---------------------------------------------------------------------------
// Kernel 1: fused embedding-gather + conv1d(k=3, SAME) + max-pool + relu
// One CTA per sentence, 256 threads (8 warps).
// Register tiling: each lane computes 4 channels x 4 contiguous positions.
// ---------------------------------------------------------------------------
__global__ void __launch_bounds__(256) enc_kernel(
    const int* __restrict__ X, const int* __restrict__ pos1,
    const int* __restrict__ pos2,
    const float* __restrict__ word_emb, const float* __restrict__ p1e,
    const float* __restrict__ p2e, const float* __restrict__ conv_w,
    const float* __restrict__ conv_b)
{
    extern __shared__ float sm[];
    float* emb_s = sm;                      // [EMB][LP] = 7920 floats
    float* w_s   = sm + EMB * LP;           // 8 warps * 720 floats
    int*   toks  = (int*)(w_s + 8 * 720);   // 3 * SL ints

    const int n   = blockIdx.x;
    const int tid = threadIdx.x;

    // --- token ids to smem
    if (tid < SL) {
        toks[tid]          = X[n * SL + tid];
        toks[SL + tid]     = pos1[n * SL + tid];
        toks[2 * SL + tid] = pos2[n * SL + tid];
    }
    // --- zero SAME-padding columns (and the 2 alignment pad columns)
    for (int e = tid; e < EMB; e += 256) {
        emb_s[e * LP + 0]   = 0.f;
        emb_s[e * LP + 129] = 0.f;
        emb_s[e * LP + 130] = 0.f;
        emb_s[e * LP + 131] = 0.f;
    }
    __syncthreads();

    // --- gather: word part (coalesced along d), transposed into [e][l+1]
    for (int idx = tid; idx < SL * VEC; idx += 256) {
        int l = idx / VEC, d = idx - l * VEC;
        emb_s[d * LP + l + 1] = word_emb[toks[l] * VEC + d];
    }
    // --- gather: position parts
    for (int idx = tid; idx < SL * PDIM; idx += 256) {
        int l = idx / PDIM, d = idx - l * PDIM;
        emb_s[(VEC + d) * LP + l + 1]        = p1e[toks[SL + l] * PDIM + d];
        emb_s[(VEC + PDIM + d) * LP + l + 1] = p2e[toks[2 * SL + l] * PDIM + d];
    }
    __syncthreads();

    const int wid  = tid >> 5;
    const int lane = tid & 31;
    const int p0   = lane << 2;          // 4 contiguous output positions per lane
    float* wbuf    = w_s + wid * 720;

    // 58 channel-groups of 4 (last has 2 real channels)
    for (int g = wid; g < 58; g += 8) {
        const int c0 = g * 4;

        // stage this group's weights, repacked as [e][c_local*3 + k] (12/row)
        __syncwarp();
        for (int t = lane; t < 720; t += 32) {
            int cl = t / 180, r = t - cl * 180;
            int e = r / 3, k = r - e * 3;
            float v = (c0 + cl < HID) ? conv_w[(c0 + cl) * 180 + r] : 0.f;
            wbuf[e * 12 + cl * 3 + k] = v;
        }
        __syncwarp();

        float acc[4][4];
        #pragma unroll
        for (int i = 0; i < 4; i++)
            #pragma unroll
            for (int j = 0; j < 4; j++) acc[i][j] = 0.f;

        #pragma unroll 2
        for (int e = 0; e < EMB; e++) {
            const float4 xa = *reinterpret_cast<const float4*>(emb_s + e * LP + p0);
            const float4 xb = *reinterpret_cast<const float4*>(emb_s + e * LP + p0 + 4);
            const float4 wA = *reinterpret_cast<const float4*>(wbuf + e * 12);
            const float4 wB = *reinterpret_cast<const float4*>(wbuf + e * 12 + 4);
            const float4 wC = *reinterpret_cast<const float4*>(wbuf + e * 12 + 8);
            float x[6] = {xa.x, xa.y, xa.z, xa.w, xb.x, xb.y};
            float w[12] = {wA.x, wA.y, wA.z, wA.w,
                           wB.x, wB.y, wB.z, wB.w,
                           wC.x, wC.y, wC.z, wC.w};
            #pragma unroll
            for (int cl = 0; cl < 4; cl++) {
                #pragma unroll
                for (int j = 0; j < 4; j++) {
                    acc[cl][j] = fmaf(x[j + 0], w[cl * 3 + 0], acc[cl][j]);
                    acc[cl][j] = fmaf(x[j + 1], w[cl * 3 + 1], acc[cl][j]);
                    acc[cl][j] = fmaf(x[j + 2], w[cl * 3 + 2], acc[cl][j]);
                }
            }
        }

        // max-pool over positions (4 local + warp butterfly), +bias, relu, store
        #pragma unroll
        for (int cl = 0; cl < 4; cl++) {
            float m = fmaxf(fmaxf(acc[cl][0], acc[cl][1]),
                            fmaxf(acc[cl][2], acc[cl][3]));
            #pragma unroll
            for (int o = 16; o > 0; o >>= 1)
                m = fmaxf(m, __shfl_xor_sync(0xffffffffu, m, o));
            if (lane == 0 && c0 + cl < HID) {
                float hv = m + conv_b[c0 + cl];
                g_h[n * HID + c0 + cl] = hv > 0.f ? hv : 0.f;
            }
        }
    }
}

// ---------------------------------------------------------------------------
// Kernel 2: per-bag softmax attention pooling + relation classifier
// One CTA per bag, 256 threads.
// ---------------------------------------------------------------------------
__global__ void __launch_bounds__(256) bag_kernel(
    const int* __restrict__ scope, const int* __restrict__ relation,
    const float* __restrict__ rel_w, const float* __restrict__ rel_b,
    float* __restrict__ out)
{
    __shared__ float rq[HID];
    __shared__ float rep[HID];
    __shared__ float logits[64];
    __shared__ float alpha[64];

    const int b    = blockIdx.x;
    const int tid  = threadIdx.x;
    const int wid  = tid >> 5;
    const int lane = tid & 31;

    const int s0 = scope[2 * b];
    const int s1 = scope[2 * b + 1];
    const int sz = s1 - s0;
    const int rel = relation[b];

    for (int d = tid; d < HID; d += 256) rq[d] = rel_w[rel * HID + d];
    __syncthreads();

    // logits: one warp per sentence in the bag
    for (int i = wid; i < sz && i < 64; i += 8) {
        const float* hr = g_h + (s0 + i) * HID;
        float s = 0.f;
        for (int d = lane; d < HID; d += 32) s += hr[d] * rq[d];
        #pragma unroll
        for (int o = 16; o > 0; o >>= 1) s += __shfl_xor_sync(0xffffffffu, s, o);
        if (lane == 0) logits[i] = s;
    }
    __syncthreads();

    // softmax over the (tiny) bag
    if (tid == 0) {
        float m = -1e30f;
        for (int i = 0; i < sz && i < 64; i++) m = fmaxf(m, logits[i]);
        float den = 0.f;
        for (int i = 0; i < sz && i < 64; i++) {
            float e = expf(logits[i] - m);
            alpha[i] = e;
            den += e;
        }
        float inv = 1.f / den;
        for (int i = 0; i < sz && i < 64; i++) alpha[i] *= inv;
    }
    __syncthreads();

    // weighted bag representation
    for (int d = tid; d < HID; d += 256) {
        float a = 0.f;
        for (int i = 0; i < sz && i < 64; i++)
            a += alpha[i] * g_h[(s0 + i) * HID + d];
        rep[d] = a;
    }
    __syncthreads();

    // classifier: one warp per relation output
    for (int r = wid; r < NREL; r += 8) {
        float s = 0.f;
        for (int d = lane; d < HID; d += 32) s += rep[d] * rel_w[r * HID + d];
        #pragma unroll
        for (int o = 16; o > 0; o >>= 1) s += __shfl_xor_sync(0xffffffffu, s, o);
        if (lane == 0) out[b * NREL + r] = s + rel_b[r];
    }
}

// ---------------------------------------------------------------------------
extern "C" void kernel_launch(void* const* d_in, const int* in_sizes, int n_in,
                              void* d_out, int out_size)
{
    const int*   X        = (const int*)d_in[0];
    const int*   pos1     = (const int*)d_in[1];
    const int*   pos2     = (const int*)d_in[2];
    // d_in[3] mask, d_in[4] length: unused by the CNN encoder
    const int*   scope    = (const int*)d_in[5];
    const int*   relation = (const int*)d_in[6];
    const float* word_emb = (const float*)d_in[7];
    const float* p1e      = (const float*)d_in[8];
    const float* p2e      = (const float*)d_in[9];
    const float* conv_w   = (const float*)d_in[10];
    const float* conv_b   = (const float*)d_in[11];
    const float* rel_w    = (const float*)d_in[12];
    const float* rel_b    = (const float*)d_in[13];
    float*       out      = (float*)d_out;

    const int smem_bytes = (EMB * LP + 8 * 720) * (int)sizeof(float)
                         + 3 * SL * (int)sizeof(int);   // 56,256 B
    cudaFuncSetAttribute(enc_kernel,
                         cudaFuncAttributeMaxDynamicSharedMemorySize, smem_bytes);

    enc_kernel<<<NS, 256, smem_bytes>>>(X, pos1, pos2, word_emb, p1e, p2e,
                                        conv_w, conv_b);
    bag_kernel<<<NBAG, 256>>>(scope, relation, rel_w, rel_b, out);
}